// round 9
// baseline (speedup 1.0000x reference)
#include <cuda_runtime.h>
#include <cuda_bf16.h>

#define Bn 2
#define Cc 32
#define Hh 32
#define Nn 128
#define Ff 32
#define Ee 16256          // N*(N-1)
#define NM1 127
#define NCHUNK 16         // 16 chunks of <=8 edges per receiver
#define LN_EPS 1e-5f

// ---------------- scratch (device globals; no allocation) ----------------
__device__ float g_A  [Bn*Hh*Nn*Ff];    // fc1(conv(sender-part))        (1 MB)
__device__ float g_Bc [Bn*Hh*Nn*Ff];    // fc1(conv(receiver-part))+bias (1 MB)
__device__ float g_part[Bn*Hh*Nn*2];    // per-(b,h,r) partial (sum, sumsq)
__device__ float g_stats[Bn*Hh*2];      // (mu, invstd) per (b,h)
__device__ float g_ipart[Bn*Nn*NCHUNK*Hh*Ff]; // incoming partials (16.8 MB)
__device__ float g_inc [Bn*Hh*Nn*Ff];   // incoming (already /N)
__device__ float g_incm[Bn*Hh*Nn*Ff];   // incoming after node MLP

__device__ __forceinline__ float silu_f(float x) {
    return x * __frcp_rn(1.f + __expf(-x));
}
__device__ __forceinline__ float sigm_f(float x) {
    return __frcp_rn(1.f + __expf(-x));
}

// ---------------- K1: per-node A / Bc precompute ----------------
__global__ void k1_node_pre(const float* __restrict__ node,
                            const float* __restrict__ ecw,
                            const float* __restrict__ ecb,
                            const float* __restrict__ f1w,
                            const float* __restrict__ f1b) {
    int bid = blockIdx.x;                 // (b,h,n) linear
    int n = bid & (Nn-1);
    int h = (bid >> 7) & (Hh-1);
    int b = bid >> 12;
    int g = threadIdx.x;

    const float* np_ = node + ((b*Cc)*Nn + n)*Ff + g;
    const float* w   = ecw + h*2*Cc;
    float S = 0.f, R = 0.f;
#pragma unroll
    for (int c = 0; c < Cc; c++) {
        float v = np_[c*Nn*Ff];
        S += w[c]      * v;
        R += w[Cc + c] * v;
    }
    float A0=0.f,A1=0.f,A2=0.f,A3=0.f, B0=0.f,B1=0.f,B2=0.f,B3=0.f, rs=0.f;
#pragma unroll
    for (int f = 0; f < Ff; f += 4) {
        float w0 = f1w[g*Ff + f+0], w1 = f1w[g*Ff + f+1];
        float w2_ = f1w[g*Ff + f+2], w3 = f1w[g*Ff + f+3];
        A0 += w0 * __shfl_sync(0xffffffffu, S, f+0);
        A1 += w1 * __shfl_sync(0xffffffffu, S, f+1);
        A2 += w2_ * __shfl_sync(0xffffffffu, S, f+2);
        A3 += w3 * __shfl_sync(0xffffffffu, S, f+3);
        B0 += w0 * __shfl_sync(0xffffffffu, R, f+0);
        B1 += w1 * __shfl_sync(0xffffffffu, R, f+1);
        B2 += w2_ * __shfl_sync(0xffffffffu, R, f+2);
        B3 += w3 * __shfl_sync(0xffffffffu, R, f+3);
        rs += w0 + w1 + w2_ + w3;
    }
    int o = ((b*Hh + h)*Nn + n)*Ff + g;
    g_A [o] = (A0+A1)+(A2+A3);
    g_Bc[o] = (B0+B1)+(B2+B3) + ecb[h]*rs + f1b[g];
}

// ---------------- K2': stats-only — x = silu(fc2(silu(A[s]+Bc[r]))), NO x store ----------------
__global__ void k2_stats(const float* __restrict__ f2w,
                         const float* __restrict__ f2b) {
    int bid = blockIdx.x;                 // (b,h,r)
    int r = bid & (Nn-1);
    int h = (bid >> 7) & (Hh-1);
    int b = bid >> 12;
    int g = threadIdx.x & 31;
    int w = threadIdx.x >> 5;             // 0..7
    int bh = b*Hh + h;

    __shared__ float su[8][2][32];        // per-warp double-buffered u stage

    float bc = g_Bc[(bh*Nn + r)*Ff + g];
    float4 w2r[8];
#pragma unroll
    for (int q = 0; q < 8; q++) w2r[q] = ((const float4*)(f2w + g*Ff))[q];
    float b2 = f2b[g];

    const float* Abase = g_A + (size_t)bh*Nn*Ff + g;
    float s1 = 0.f, s2 = 0.f;
    int buf = 0;
    for (int j = w; j < NM1; j += 8) {
        int s = j + (j >= r);
        float u = silu_f(Abase[s*Ff] + bc);
        su[w][buf][g] = u;
        __syncwarp();
        float v0=0.f,v1=0.f,v2=0.f,v3=0.f;
#pragma unroll
        for (int q = 0; q < 8; q++) {
            float4 u4 = *(const float4*)&su[w][buf][q*4];
            v0 += u4.x * w2r[q].x;
            v1 += u4.y * w2r[q].y;
            v2 += u4.z * w2r[q].z;
            v3 += u4.w * w2r[q].w;
        }
        float x = silu_f(b2 + ((v0+v1)+(v2+v3)));
        s1 += x; s2 += x*x;
        buf ^= 1;
    }
#pragma unroll
    for (int o = 16; o; o >>= 1) {
        s1 += __shfl_down_sync(0xffffffffu, s1, o);
        s2 += __shfl_down_sync(0xffffffffu, s2, o);
    }
    __shared__ float sm[16];
    if (g == 0) { sm[w] = s1; sm[8 + w] = s2; }
    __syncthreads();
    if (threadIdx.x == 0) {
        float t1 = 0.f, t2 = 0.f;
#pragma unroll
        for (int q = 0; q < 8; q++) { t1 += sm[q]; t2 += sm[8+q]; }
        g_part[(bh*Nn + r)*2 + 0] = t1;
        g_part[(bh*Nn + r)*2 + 1] = t2;
    }
}

// ---------------- K3: finalize LN stats per (b,h) ----------------
__global__ void k3_stats() {
    int bh = blockIdx.x;
    int t  = threadIdx.x;                 // 0..127 = r
    float s1 = g_part[(bh*Nn + t)*2 + 0];
    float s2 = g_part[(bh*Nn + t)*2 + 1];
#pragma unroll
    for (int o = 16; o; o >>= 1) {
        s1 += __shfl_down_sync(0xffffffffu, s1, o);
        s2 += __shfl_down_sync(0xffffffffu, s2, o);
    }
    __shared__ float sm[8];
    if ((t & 31) == 0) { sm[t >> 5] = s1; sm[4 + (t >> 5)] = s2; }
    __syncthreads();
    if (t == 0) {
        float T1 = sm[0] + sm[1] + sm[2] + sm[3];
        float T2 = sm[4] + sm[5] + sm[6] + sm[7];
        const float invc = 1.f / (float)(Ee * Ff);
        float mu  = T1 * invc;
        float var = T2 * invc - mu*mu;
        g_stats[bh*2 + 0] = mu;
        g_stats[bh*2 + 1] = rsqrtf(var + LN_EPS);
    }
}

// ---------------- K4f: fused recompute + LN + att + mij + inc partials ----------------
// block = (b, r, chunk of <=8 edges); grid = Bn*Nn*NCHUNK = 4096; 256 threads.
__global__ void k4_fused(const float* __restrict__ emask,
                         const float* __restrict__ lng,
                         const float* __restrict__ lnb,
                         const float* __restrict__ attw,
                         const float* __restrict__ attb,
                         const float* __restrict__ f2w,
                         const float* __restrict__ f2b,
                         float* __restrict__ out_mij) {
    int c = blockIdx.x & (NCHUNK-1);
    int r = (blockIdx.x >> 4) & (Nn-1);
    int b = blockIdx.x >> 11;
    int tid = threadIdx.x;
    int g = tid & 31, w = tid >> 5;       // phase1: lane g, warp=edge w

    __shared__ float sBc[Hh][Ff];         // 4 KB
    __shared__ float xT[Hh*264];          // 33 KB, padded rows (264 floats per h)
    __shared__ float su[8][32];
    __shared__ float sT[8][32];
    __shared__ float satt[8][32], slg[8][32], slb[8][32];
    __shared__ float smu[Hh], sinv[Hh], swh[Hh];
    __shared__ float sem[8];
    __shared__ float sc[4];               // c1, c0, ab

    int j0 = c*8;
    int nE = NM1 - j0; if (nE > 8) nE = 8;

    if (tid < Hh) {
        float mu = g_stats[(b*Hh + tid)*2 + 0];
        float iv = g_stats[(b*Hh + tid)*2 + 1];
        smu[tid] = mu; sinv[tid] = iv; swh[tid] = attw[tid]*iv;
    }
    {   // Bc tile: 32 rows x 32 f, one float4 per thread
        int hh = tid >> 3, q = tid & 7;
        ((float4*)&sBc[hh][0])[q] =
            ((const float4*)(g_Bc + ((size_t)(b*Hh + hh)*Nn + r)*Ff))[q];
    }
    __syncthreads();
    if (tid == 0) {
        float c1 = 0.f, c0 = 0.f;
#pragma unroll
        for (int h = 0; h < Hh; h++) { c1 += swh[h]*smu[h]; c0 += attw[h]; }
        sc[0] = c1; sc[1] = c0; sc[2] = attb[0];
    }

    // ---- phase 1: recompute x for all h (warp = one edge) ----
    float4 w2r[8];
#pragma unroll
    for (int q = 0; q < 8; q++) w2r[q] = ((const float4*)(f2w + g*Ff))[q];
    float b2 = f2b[g];

    if (w < nE) {
        int j = j0 + w;
        int s = j + (j >= r);
        const float* Ap = g_A + ((size_t)(b*Hh)*Nn + s)*Ff + g;  // +h*Nn*Ff per h
        float regT = 0.f;
#pragma unroll 2
        for (int h = 0; h < Hh; h++) {
            float u = silu_f(Ap[(size_t)h*Nn*Ff] + sBc[h][g]);
            su[w][g] = u;
            __syncwarp();
            float v0=0.f,v1=0.f,v2=0.f,v3=0.f;
#pragma unroll
            for (int q = 0; q < 8; q++) {
                float4 u4 = *(const float4*)&su[w][q*4];
                v0 += u4.x * w2r[q].x;
                v1 += u4.y * w2r[q].y;
                v2 += u4.z * w2r[q].z;
                v3 += u4.w * w2r[q].w;
            }
            __syncwarp();
            float x = silu_f(b2 + ((v0+v1)+(v2+v3)));
            xT[h*264 + w*32 + g] = x;
            regT += swh[h]*x;
        }
        sT[w][g] = regT;
    }
    __syncthreads();

    // ---- phase 2: attention per (e,f), stage lg/lb/em/att ----
    {
        int e = tid >> 5, f = tid & 31;
        if (e < nE) {
            int eg = r*NM1 + j0 + e;
            float em = emask[b*Ee + eg];
            float lg = lng[eg*Ff + f];
            float lb = lnb[eg*Ff + f];
            float T  = sT[e][f];
            satt[e][f] = sigm_f(em*(lg*(T - sc[0]) + lb*sc[1]) + sc[2]);
            slg[e][f] = lg; slb[e][f] = lb;
            if (f == 0) sem[e] = em;
        }
    }
    __syncthreads();

    // ---- phase 3: mij writes + incoming partials; thread = (h, f-quad) ----
    {
        int h = tid >> 3, f4 = tid & 7;
        float mu = smu[h], iv = sinv[h];
        float4* mo = (float4*)out_mij + ((size_t)(b*Hh + h)*Ee + r*NM1 + j0)*8 + f4;
        float4 acc = make_float4(0.f, 0.f, 0.f, 0.f);
        for (int e = 0; e < nE; e++) {
            float em = sem[e];
            float4 x  = *(float4*)&xT[h*264 + e*32 + f4*4];
            float4 lg = *(float4*)&slg[e][f4*4];
            float4 lb = *(float4*)&slb[e][f4*4];
            float4 at = *(float4*)&satt[e][f4*4];
            float4 m1, mv;
            m1.x = ((x.x - mu)*iv*lg.x + lb.x) * em;
            m1.y = ((x.y - mu)*iv*lg.y + lb.y) * em;
            m1.z = ((x.z - mu)*iv*lg.z + lb.z) * em;
            m1.w = ((x.w - mu)*iv*lg.w + lb.w) * em;
            mv.x = m1.x*em; mv.y = m1.y*em; mv.z = m1.z*em; mv.w = m1.w*em;
            mo[e*8] = mv;
            acc.x += m1.x*at.x*em;
            acc.y += m1.y*at.y*em;
            acc.z += m1.z*at.z*em;
            acc.w += m1.w*at.w*em;
        }
        *(float4*)&g_ipart[((size_t)(b*Nn + r)*NCHUNK + c)*(Hh*Ff) + h*Ff + f4*4] = acc;
    }
}

// ---------------- K5: reduce incoming partials (deterministic) ----------------
// grid Bn*Nn, 256 threads; thread i = float4 slot over (h,f).
__global__ void k5_inc_reduce() {
    int br = blockIdx.x;                  // b*Nn + r
    int b = br >> 7, r = br & (Nn-1);
    int i = threadIdx.x;                  // 0..255 float4 slots (h = i>>3, f4 = i&7)
    const float4* p = (const float4*)(g_ipart + (size_t)br*NCHUNK*(Hh*Ff)) + i;
    float4 s = make_float4(0.f, 0.f, 0.f, 0.f);
#pragma unroll
    for (int cg = 0; cg < NCHUNK; cg++) {
        float4 v = p[(size_t)cg*(Hh*Ff/4)];
        s.x += v.x; s.y += v.y; s.z += v.z; s.w += v.w;
    }
    const float invN = 1.f/(float)Nn;
    s.x *= invN; s.y *= invN; s.z *= invN; s.w *= invN;
    int h = i >> 3, f4 = i & 7;
    *(float4*)&g_inc[((size_t)(b*Hh + h)*Nn + r)*Ff + f4*4] = s;
}

// ---------------- node-side MLP4d: one block per (b,h'), whole LN in-block ----------------
template<int MODE>
__global__ void k_node_mlp(const float* __restrict__ node,
                           const float* __restrict__ cw,
                           const float* __restrict__ cb,
                           const float* __restrict__ f1w,
                           const float* __restrict__ f1b,
                           const float* __restrict__ f2w,
                           const float* __restrict__ f2b,
                           const float* __restrict__ lg,
                           const float* __restrict__ lb,
                           const float* __restrict__ nmask,
                           float* __restrict__ out) {
    int hp = blockIdx.x & (Hh-1);
    int b  = blockIdx.x >> 5;
    int f  = threadIdx.x & 31;
    int w  = threadIdx.x >> 5;            // 0..3

    const int NCH = (MODE == 0) ? Hh : 2*Hh;
    __shared__ float scw[2*Hh];
    __shared__ float su[Nn*Ff];           // 16 KB
    __shared__ float sred[8];
    __shared__ float sstat[2];
    for (int i = threadIdx.x; i < NCH; i += blockDim.x) scw[i] = cw[hp*NCH + i];
    __syncthreads();

    float w1r[Ff], w2r[Ff];
#pragma unroll
    for (int q = 0; q < Ff; q++) { w1r[q] = f1w[f*Ff + q]; w2r[q] = f2w[f*Ff + q]; }
    float cbv = cb[hp], b1 = f1b[f], b2 = f2b[f];

    float s1 = 0.f, s2 = 0.f;
    for (int n = w; n < Nn; n += 4) {
        float y = cbv;
        if (MODE == 0) {
            const float* ip = g_inc + ((b*Hh)*Nn + n)*Ff + f;
#pragma unroll
            for (int h = 0; h < Hh; h++) y += scw[h] * ip[h*Nn*Ff];
        } else {
            const float* ipa = node   + ((b*Cc)*Nn + n)*Ff + f;
            const float* ipb = g_incm + ((b*Hh)*Nn + n)*Ff + f;
#pragma unroll
            for (int c = 0; c < Cc; c++) y += scw[c] * ipa[c*Nn*Ff];
#pragma unroll
            for (int h = 0; h < Hh; h++) y += scw[Cc + h] * ipb[h*Nn*Ff];
        }
        float a0=0.f,a1=0.f,a2=0.f,a3=0.f;
#pragma unroll
        for (int q = 0; q < Ff; q += 4) {
            a0 += __shfl_sync(0xffffffffu, y, q+0) * w1r[q+0];
            a1 += __shfl_sync(0xffffffffu, y, q+1) * w1r[q+1];
            a2 += __shfl_sync(0xffffffffu, y, q+2) * w1r[q+2];
            a3 += __shfl_sync(0xffffffffu, y, q+3) * w1r[q+3];
        }
        float u1 = silu_f(b1 + ((a0+a1)+(a2+a3)));
        a0=a1=a2=a3=0.f;
#pragma unroll
        for (int q = 0; q < Ff; q += 4) {
            a0 += __shfl_sync(0xffffffffu, u1, q+0) * w2r[q+0];
            a1 += __shfl_sync(0xffffffffu, u1, q+1) * w2r[q+1];
            a2 += __shfl_sync(0xffffffffu, u1, q+2) * w2r[q+2];
            a3 += __shfl_sync(0xffffffffu, u1, q+3) * w2r[q+3];
        }
        float u2 = silu_f(b2 + ((a0+a1)+(a2+a3)));
        su[n*Ff + f] = u2;
        s1 += u2; s2 += u2*u2;
    }
#pragma unroll
    for (int o = 16; o; o >>= 1) {
        s1 += __shfl_down_sync(0xffffffffu, s1, o);
        s2 += __shfl_down_sync(0xffffffffu, s2, o);
    }
    if (f == 0) { sred[w] = s1; sred[4 + w] = s2; }
    __syncthreads();
    if (threadIdx.x == 0) {
        float T1 = sred[0] + sred[1] + sred[2] + sred[3];
        float T2 = sred[4] + sred[5] + sred[6] + sred[7];
        const float invc = 1.f / (float)(Nn * Ff);
        float mu  = T1 * invc;
        float var = T2 * invc - mu*mu;
        sstat[0] = mu;
        sstat[1] = rsqrtf(var + LN_EPS);
    }
    __syncthreads();
    float mu = sstat[0], inv = sstat[1];
    for (int n = w; n < Nn; n += 4) {
        float v = (su[n*Ff + f] - mu) * inv * lg[n*Ff + f] + lb[n*Ff + f];
        int oidx = ((b*Hh + hp)*Nn + n)*Ff + f;
        if (MODE == 0) {
            g_incm[oidx] = v;
        } else {
            out[oidx] = v * nmask[b*Nn + n];
        }
    }
}

// ---------------- launch ----------------
extern "C" void kernel_launch(void* const* d_in, const int* in_sizes, int n_in,
                              void* d_out, int out_size) {
    const float* node   = (const float*)d_in[0];
    const float* nmask  = (const float*)d_in[3];
    const float* emask  = (const float*)d_in[4];
    const float* e_cw   = (const float*)d_in[5];
    const float* e_cb   = (const float*)d_in[6];
    const float* e_f1w  = (const float*)d_in[7];
    const float* e_f1b  = (const float*)d_in[8];
    const float* e_f2w  = (const float*)d_in[9];
    const float* e_f2b  = (const float*)d_in[10];
    const float* e_lng  = (const float*)d_in[11];
    const float* e_lnb  = (const float*)d_in[12];
    const float* att_w  = (const float*)d_in[13];
    const float* att_b  = (const float*)d_in[14];
    const float* n_cw   = (const float*)d_in[15];
    const float* n_cb   = (const float*)d_in[16];
    const float* n_f1w  = (const float*)d_in[17];
    const float* n_f1b  = (const float*)d_in[18];
    const float* n_f2w  = (const float*)d_in[19];
    const float* n_f2b  = (const float*)d_in[20];
    const float* n_lng  = (const float*)d_in[21];
    const float* n_lnb  = (const float*)d_in[22];
    const float* ne_cw  = (const float*)d_in[23];
    const float* ne_cb  = (const float*)d_in[24];
    const float* ne_f1w = (const float*)d_in[25];
    const float* ne_f1b = (const float*)d_in[26];
    const float* ne_f2w = (const float*)d_in[27];
    const float* ne_f2b = (const float*)d_in[28];
    const float* ne_lng = (const float*)d_in[29];
    const float* ne_lnb = (const float*)d_in[30];

    float* out_node = (float*)d_out;                       // (B,H,N,F)
    float* out_mij  = (float*)d_out + Bn*Hh*Nn*Ff;         // (B,H,E,F)

    k1_node_pre<<<Bn*Hh*Nn, 32>>>(node, e_cw, e_cb, e_f1w, e_f1b);
    k2_stats   <<<Bn*Hh*Nn, 256>>>(e_f2w, e_f2b);
    k3_stats   <<<Bn*Hh, 128>>>();
    k4_fused   <<<Bn*Nn*NCHUNK, 256>>>(emask, e_lng, e_lnb, att_w, att_b,
                                       e_f2w, e_f2b, out_mij);
    k5_inc_reduce<<<Bn*Nn, 256>>>();
    k_node_mlp<0><<<Bn*Hh, 128>>>(nullptr, n_cw, n_cb, n_f1w, n_f1b,
                                  n_f2w, n_f2b, n_lng, n_lnb, nullptr, nullptr);
    k_node_mlp<1><<<Bn*Hh, 128>>>(node, ne_cw, ne_cb, ne_f1w, ne_f1b,
                                  ne_f2w, ne_f2b, ne_lng, ne_lnb, nmask, out_node);
}